// round 1
// baseline (speedup 1.0000x reference)
#include <cuda_runtime.h>
#include <cstdint>

// Moment feature expansion, order 4, latent dim 16.
// out[b,t,:] = [1, x(16), f2(136), f3(816), f4(3876)]  -> 4845 channels
// f_{o+1}[m] = f_o[k_m] * x[j_m], (k,j) pairs replicate the reference's
// np.nonzero(keep) row-major enumeration exactly.

#define D    16
#define N2   136
#define N3   816
#define N4   3876
#define NOUT 4845   // 1 + 16 + 136 + 816 + 3876

struct Tab2 { uint16_t v[N2]; };
struct Tab3 { uint16_t v[N3]; };
struct Tab4 { uint16_t v[N4]; };

// Order-2: pairs (k, j) with 0 <= j <= k < 16, k-major.
constexpr Tab2 gen2() {
    Tab2 t{}; int m = 0;
    for (int k = 0; k < D; k++)
        for (int j = 0; j <= k; j++)
            t.v[m++] = (uint16_t)((k << 4) | j);
    return t;
}

// Order-3: offsets2[j] = 136 - (16-j)(17-j)/2 ; keep (k,j) iff k >= offsets2[j].
constexpr Tab3 gen3() {
    Tab3 t{}; int m = 0;
    int off[D] = {};
    for (int j = 0; j < D; j++)
        off[j] = N2 - (D - j) * (D - j + 1) / 2;
    for (int k = 0; k < N2; k++)
        for (int j = 0; j < D; j++)
            if (k >= off[j]) t.v[m++] = (uint16_t)((k << 4) | j);
    return t;
}

// Order-4: offsets3[j] = 816 - C(18-j, 3) ; keep (k,j) iff k >= offsets3[j].
constexpr Tab4 gen4() {
    Tab4 t{}; int m = 0;
    int off[D] = {};
    for (int j = 0; j < D; j++) {
        int a = D + 2 - j;                      // 18 - j
        off[j] = N3 - a * (a - 1) * (a - 2) / 6;
    }
    for (int k = 0; k < N3; k++)
        for (int j = 0; j < D; j++)
            if (k >= off[j]) t.v[m++] = (uint16_t)((k << 4) | j);
    return t;
}

__device__ constexpr Tab2 c_t2 = gen2();
__device__ constexpr Tab3 c_t3 = gen3();
__device__ constexpr Tab4 c_t4 = gen4();

#define NTHREADS 256

__global__ __launch_bounds__(NTHREADS)
void Moment_2774548873409_kernel(const float* __restrict__ in,
                                 float* __restrict__ out,
                                 int rows) {
    __shared__ float sx[D];
    __shared__ float sf2[N2];
    __shared__ float sf3[N3];

    const int row = blockIdx.x;
    if (row >= rows) return;

    const float* __restrict__ xin = in + (size_t)row * D;
    float* __restrict__ o = out + (size_t)row * NOUT;

    const int t = threadIdx.x;

    // --- order 0 and 1 ---
    if (t < D) {
        float v = xin[t];
        sx[t] = v;
        o[1 + t] = v;
    }
    if (t == 0) o[0] = 1.0f;
    __syncthreads();

    // --- order 2: f2[m] = x[k] * x[j] ---
    if (t < N2) {
        uint16_t p = c_t2.v[t];
        float v = sx[p >> 4] * sx[p & 15];
        sf2[t] = v;
        o[1 + D + t] = v;
    }
    __syncthreads();

    // --- order 3: f3[m] = f2[k] * x[j] ---
    #pragma unroll
    for (int m = t; m < N3; m += NTHREADS) {
        uint16_t p = c_t3.v[m];
        float v = sf2[p >> 4] * sx[p & 15];
        sf3[m] = v;
        o[1 + D + N2 + m] = v;
    }
    __syncthreads();

    // --- order 4: out = f3[k] * x[j], streamed straight to GMEM ---
    #pragma unroll
    for (int m = t; m < N4; m += NTHREADS) {
        uint16_t p = c_t4.v[m];
        o[1 + D + N2 + N3 + m] = sf3[p >> 4] * sx[p & 15];
    }
}

extern "C" void kernel_launch(void* const* d_in, const int* in_sizes, int n_in,
                              void* d_out, int out_size) {
    const float* in = (const float*)d_in[0];
    float* out = (float*)d_out;
    const int rows = in_sizes[0] / D;   // 4 * 2048 = 8192
    Moment_2774548873409_kernel<<<rows, NTHREADS>>>(in, out, rows);
}